// round 3
// baseline (speedup 1.0000x reference)
#include <cuda_runtime.h>
#include <math.h>

#define BB   16
#define TT   8000
#define TN   800
#define HID  512
#define LAT  128
#define KCB  1024
#define NQ   4
#define COUNT_DEC 1599
#define NCHUNKS   25584   // BB * COUNT_DEC
#define RESCORE_TAU 4e-3f

// ---------------- scratch (device globals; no allocation allowed) ----------------
__device__ float g_z1[BB*HID*TN];        // enc1 out (B,512,800)
__device__ float g_z2[(size_t)BB*HID*TT];// pooled+interp (B,512,8000)
__device__ float g_z3[(size_t)BB*HID*TT];// enc2a out (B,512,8000)
__device__ float g_ze[(size_t)BB*TT*LAT];// enc2b out, transposed (B,T,128)
__device__ float g_res[(size_t)BB*TT*LAT];
__device__ float g_qout[(size_t)BB*TT*LAT];
__device__ int   g_codes[BB*TT*NQ];
__device__ float g_cbn[NQ*KCB];
__device__ double g_acc[8];  // [0..3] vq sums, [4] smooth count, [5] recon sum

// ---------------- tiny utility kernels ----------------
__global__ void k_zero_acc() {
    if (threadIdx.x < 8) g_acc[threadIdx.x] = 0.0;
}

// ---------------- enc1: (B,20,800) -> relu conv K=3 -> (B,512,800) ----------------
__global__ __launch_bounds__(256) void k_enc1(const float* __restrict__ traj,
                                              const float* __restrict__ w,
                                              const float* __restrict__ bias) {
    __shared__ float xs[20][18];
    int b = blockIdx.y, t0 = blockIdx.x * 16;
    int tid = threadIdx.x;
    for (int e = tid; e < 20*18; e += 256) {
        int i = e / 18, u = e % 18;
        int tg = t0 + u - 1;
        float v = 0.f;
        if (tg >= 0 && tg < TN) v = traj[((size_t)b*2 + (i/10))*TT + tg*10 + (i%10)];
        xs[i][u] = v;
    }
    __syncthreads();
    int o0 = tid, o1 = tid + 256;
    float acc0[16], acc1[16];
    float b0 = bias[o0], b1v = bias[o1];
    #pragma unroll
    for (int t = 0; t < 16; t++) { acc0[t] = 0.f; acc1[t] = 0.f; }
    for (int i = 0; i < 20; i++) {
        #pragma unroll
        for (int j = 0; j < 3; j++) {
            float w0 = w[(o0*20 + i)*3 + j];
            float w1 = w[(o1*20 + i)*3 + j];
            #pragma unroll
            for (int t = 0; t < 16; t++) {
                float x = xs[i][t + j];
                acc0[t] += w0 * x;
                acc1[t] += w1 * x;
            }
        }
    }
    #pragma unroll
    for (int t = 0; t < 16; t++) {
        g_z1[((size_t)b*HID + o0)*TN + t0 + t] = fmaxf(acc0[t] + b0, 0.f);
        g_z1[((size_t)b*HID + o1)*TN + t0 + t] = fmaxf(acc1[t] + b1v, 0.f);
    }
}

// ---------------- pool(800->4000 repeat) + linear interp(4000->8000) ----------------
__global__ void k_z2() {
    size_t idx = (size_t)blockIdx.x * 256 + threadIdx.x;
    if (idx >= (size_t)BB*HID*TT) return;
    int t = (int)(idx % TT);
    size_t bc = idx / TT;
    const float* row = g_z1 + bc * TN;
    float src = fmaxf(((float)t + 0.5f) * 0.5f - 0.5f, 0.0f);
    int i0 = (int)src;                 // floor, src >= 0
    int i1 = min(i0 + 1, 3999);
    float frac = src - (float)i0;
    float v0 = row[i0 / 5];
    float v1 = row[i1 / 5];
    g_z2[idx] = v0 * (1.0f - frac) + v1 * frac;
}

// ---------------- generic conv (IC=512), 64x64 tile, 4x4 reg blocking ----------------
// fp32 inner chunks (32 ics = 160*K/5 terms) flushed into fp64 accumulators.
template<int K, bool RELU, bool TROUT>
__global__ __launch_bounds__(256) void k_conv(const float* __restrict__ in,
                                              const float* __restrict__ wt,
                                              const float* __restrict__ bias,
                                              float* __restrict__ out) {
    const int P = (K - 1) / 2;
    const int ZW = 64 + K - 1;
    __shared__ float wsm[8 * K * 64];
    __shared__ float zsm[8 * (64 + K - 1)];
    int tid = threadIdx.x;
    int tx = tid & 15, ty = tid >> 4;
    int t0 = blockIdx.x * 64, ob = blockIdx.y * 64, b = blockIdx.z;
    int OCt = gridDim.y * 64;
    int o = ob + ty * 4, tt = tx * 4;
    float  acc[4][4];
    double dacc[4][4];
    #pragma unroll
    for (int a = 0; a < 4; a++)
        #pragma unroll
        for (int c = 0; c < 4; c++) { acc[a][c] = 0.f; dacc[a][c] = 0.0; }

    for (int chunk = 0; chunk < 64; chunk++) {
        int ic0 = chunk * 8;
        __syncthreads();
        for (int e = tid; e < 8 * K * 64; e += 256) {
            int ol = e & 63, rest = e >> 6;
            int j = rest % K, i = rest / K;
            wsm[(i*K + j)*64 + ol] = wt[((size_t)(ob + ol)*512 + ic0 + i)*K + j];
        }
        for (int e = tid; e < 8 * ZW; e += 256) {
            int i = e / ZW, u = e % ZW;
            int tg = t0 + u - P;
            float v = 0.f;
            if (tg >= 0 && tg < TT) v = in[((size_t)b*512 + ic0 + i)*TT + tg];
            zsm[i*ZW + u] = v;
        }
        __syncthreads();
        #pragma unroll
        for (int i = 0; i < 8; i++) {
            float zr[K + 3];
            #pragma unroll
            for (int u = 0; u < K + 3; u++) zr[u] = zsm[i*ZW + tt + u];
            #pragma unroll
            for (int j = 0; j < K; j++) {
                float4 wv = *(const float4*)&wsm[(i*K + j)*64 + ty*4];
                #pragma unroll
                for (int tl = 0; tl < 4; tl++) {
                    float z = zr[tl + j];
                    acc[0][tl] += wv.x * z;
                    acc[1][tl] += wv.y * z;
                    acc[2][tl] += wv.z * z;
                    acc[3][tl] += wv.w * z;
                }
            }
        }
        if ((chunk & 3) == 3) {   // flush fp32 partial into fp64 every 32 ics
            #pragma unroll
            for (int a = 0; a < 4; a++)
                #pragma unroll
                for (int c = 0; c < 4; c++) { dacc[a][c] += (double)acc[a][c]; acc[a][c] = 0.f; }
        }
    }
    float res[4][4];
    #pragma unroll
    for (int ol = 0; ol < 4; ol++) {
        float bv = bias[o + ol];
        #pragma unroll
        for (int tl = 0; tl < 4; tl++) {
            float v = (float)dacc[ol][tl] + bv;
            if (RELU) v = fmaxf(v, 0.f);
            res[ol][tl] = v;
        }
    }
    if (!TROUT) {
        #pragma unroll
        for (int ol = 0; ol < 4; ol++) {
            float4 v = make_float4(res[ol][0], res[ol][1], res[ol][2], res[ol][3]);
            *(float4*)&out[((size_t)b*OCt + o + ol)*TT + t0 + tt] = v;
        }
    } else {
        #pragma unroll
        for (int tl = 0; tl < 4; tl++) {
            float4 v = make_float4(res[0][tl], res[1][tl], res[2][tl], res[3][tl]);
            *(float4*)&out[((size_t)b*TT + t0 + tt + tl)*OCt + o] = v;
        }
    }
}

// ---------------- codebook squared norms (double, stored fp32) ----------------
__global__ void k_cbnorm(const float* __restrict__ cb) {
    int id = blockIdx.x * 256 + threadIdx.x;
    if (id >= NQ * KCB) return;
    const float* r = cb + (size_t)id * LAT;
    double s = 0.0;
    for (int d = 0; d < LAT; d++) {
        double v = (double)r[d];
        s += v * v;
    }
    g_cbn[id] = (float)s;
}

// ---------------- residual VQ, one codebook per launch ----------------
__global__ __launch_bounds__(256) void k_vq(const float* __restrict__ cb_all, int qi) {
    extern __shared__ float sm[];
    float* rsm = sm;                      // 64 x 132
    float* csm = sm + 64*132;             // 128 x 132
    float* nsm = csm + 128*132;           // 128
    int tid = threadIdx.x, lane = tid & 31, w = tid >> 5;
    int row0 = blockIdx.x * 64;
    const float* src = (qi == 0) ? g_ze : g_res;
    for (int e = tid; e < 64*32; e += 256) {
        int lr = e >> 5, d4 = (e & 31) * 4;
        float4 v = *(const float4*)&src[(size_t)(row0 + lr)*LAT + d4];
        *(float4*)&rsm[lr*132 + d4] = v;
    }
    const float* cbq = cb_all + (size_t)qi * KCB * LAT;
    float bestv[8], secv[8]; int besti[8];
    #pragma unroll
    for (int rr = 0; rr < 8; rr++) { bestv[rr] = 3.4e38f; secv[rr] = 3.4e38f; besti[rr] = 0; }

    for (int cc = 0; cc < 8; cc++) {
        __syncthreads();
        for (int e = tid; e < 128*32; e += 256) {
            int k = e >> 5, d4 = (e & 31) * 4;
            float4 v = *(const float4*)&cbq[(size_t)(cc*128 + k)*LAT + d4];
            *(float4*)&csm[k*132 + d4] = v;
        }
        if (tid < 128) nsm[tid] = g_cbn[qi*KCB + cc*128 + tid];
        __syncthreads();
        float acc[8][4];
        #pragma unroll
        for (int rr = 0; rr < 8; rr++)
            #pragma unroll
            for (int c = 0; c < 4; c++) acc[rr][c] = 0.f;
        #pragma unroll 2
        for (int d = 0; d < 128; d += 4) {
            float4 cv[4];
            #pragma unroll
            for (int c = 0; c < 4; c++) cv[c] = *(const float4*)&csm[(lane*4 + c)*132 + d];
            #pragma unroll
            for (int rr = 0; rr < 8; rr++) {
                float4 rv = *(const float4*)&rsm[(w*8 + rr)*132 + d];
                #pragma unroll
                for (int c = 0; c < 4; c++) {
                    acc[rr][c] += rv.x*cv[c].x + rv.y*cv[c].y + rv.z*cv[c].z + rv.w*cv[c].w;
                }
            }
        }
        #pragma unroll
        for (int rr = 0; rr < 8; rr++) {
            #pragma unroll
            for (int c = 0; c < 4; c++) {
                float dist = nsm[lane*4 + c] - 2.0f * acc[rr][c];
                int idx = cc*128 + lane*4 + c;
                if (dist < bestv[rr]) { secv[rr] = bestv[rr]; bestv[rr] = dist; besti[rr] = idx; }
                else if (dist < secv[rr]) { secv[rr] = dist; }
            }
        }
    }

    double dq_local = 0.0;
    for (int rr = 0; rr < 8; rr++) {
        float v1 = bestv[rr]; int i1 = besti[rr]; float v2 = secv[rr];
        #pragma unroll
        for (int off = 16; off > 0; off >>= 1) {
            float ov1 = __shfl_xor_sync(0xffffffffu, v1, off);
            int   oi1 = __shfl_xor_sync(0xffffffffu, i1, off);
            float ov2 = __shfl_xor_sync(0xffffffffu, v2, off);
            if (ov1 < v1 || (ov1 == v1 && oi1 < i1)) {
                v2 = fminf(v1, ov2);
                v1 = ov1; i1 = oi1;
            } else {
                v2 = fminf(v2, ov1);
            }
        }
        int ix = i1;
        int rloc = w*8 + rr;
        // ---- exact fp64 rescore when the fp32 margin is too small ----
        if (v2 - v1 < RESCORE_TAU) {
            double bd = 1e300; int bi = 0x7fffffff;
            for (int kk = 0; kk < 32; kk++) {
                int k = kk*32 + lane;
                const float* cr = cbq + (size_t)k * LAT;
                double s = 0.0;
                for (int d = 0; d < 128; d++) {
                    double cd = (double)cr[d];
                    double rd = (double)rsm[rloc*132 + d];
                    s += cd*cd - 2.0*rd*cd;
                }
                if (s < bd || (s == bd && k < bi)) { bd = s; bi = k; }
            }
            #pragma unroll
            for (int off = 16; off > 0; off >>= 1) {
                double ob = __shfl_xor_sync(0xffffffffu, bd, off);
                int    oi = __shfl_xor_sync(0xffffffffu, bi, off);
                if (ob < bd || (ob == bd && oi < bi)) { bd = ob; bi = oi; }
            }
            ix = bi;
        }

        int r = row0 + rloc;
        const float* q = cbq + (size_t)ix * LAT;
        float4 qv = *(const float4*)&q[lane*4];
        float4 rv = *(const float4*)&rsm[rloc*132 + lane*4];
        double r2 = (double)rv.x*rv.x + (double)rv.y*rv.y + (double)rv.z*rv.z + (double)rv.w*rv.w;
        double q2 = (double)qv.x*qv.x + (double)qv.y*qv.y + (double)qv.z*qv.z + (double)qv.w*qv.w;
        double rq = (double)rv.x*qv.x + (double)rv.y*qv.y + (double)rv.z*qv.z + (double)rv.w*qv.w;
        double dxd = (double)qv.x - rv.x, dyd = (double)qv.y - rv.y;
        double dzd = (double)qv.z - rv.z, dwd = (double)qv.w - rv.w;
        double dq = dxd*dxd + dyd*dyd + dzd*dzd + dwd*dwd;
        #pragma unroll
        for (int off = 16; off > 0; off >>= 1) {
            r2 += __shfl_xor_sync(0xffffffffu, r2, off);
            q2 += __shfl_xor_sync(0xffffffffu, q2, off);
            rq += __shfl_xor_sync(0xffffffffu, rq, off);
            dq += __shfl_xor_sync(0xffffffffu, dq, off);
        }
        double ns = sqrt(r2), nt = sqrt(q2);
        double ins = 1.0 / (ns + 1e-12), intq = 1.0 / (nt + 1e-12);
        double ru = r2 * ins;                                        // r . u
        double ss2 = r2*ins*ins + 2.0*rq*ins*intq + q2*intq*intq;    // ||u+qh||^2
        double wn = sqrt(ss2);
        double iw = 1.0 / (wn + 1e-12);
        double rs = ru + rq * intq;                                  // r . (u+qh)
        double rw = rs * iw;                                         // r . w
        double scale = nt * ins;
        float4 qrf;
        {
            double sx = (double)rv.x*ins + (double)qv.x*intq;
            double sy = (double)rv.y*ins + (double)qv.y*intq;
            double sz = (double)rv.z*ins + (double)qv.z*intq;
            double sw = (double)rv.w*ins + (double)qv.w*intq;
            qrf.x = (float)(((double)rv.x - 2.0*rw*(sx*iw) + 2.0*ru*((double)qv.x*intq)) * scale);
            qrf.y = (float)(((double)rv.y - 2.0*rw*(sy*iw) + 2.0*ru*((double)qv.y*intq)) * scale);
            qrf.z = (float)(((double)rv.z - 2.0*rw*(sz*iw) + 2.0*ru*((double)qv.z*intq)) * scale);
            qrf.w = (float)(((double)rv.w - 2.0*rw*(sw*iw) + 2.0*ru*((double)qv.w*intq)) * scale);
        }
        size_t base = (size_t)r * LAT + lane*4;
        if (qi == 0) {
            *(float4*)&g_qout[base] = qrf;
        } else {
            float4 old = *(const float4*)&g_qout[base];
            old.x += qrf.x; old.y += qrf.y; old.z += qrf.z; old.w += qrf.w;
            *(float4*)&g_qout[base] = old;
        }
        if (qi < 3) {
            float4 nr = make_float4(rv.x - qrf.x, rv.y - qrf.y, rv.z - qrf.z, rv.w - qrf.w);
            *(float4*)&g_res[base] = nr;
        }
        if (lane == 0) {
            g_codes[r*NQ + qi] = ix;
            dq_local += dq;
        }
    }
    if (lane == 0) atomicAdd(&g_acc[qi], dq_local);
}

// ---------------- smooth loss ----------------
__global__ void k_smooth() {
    int idx = blockIdx.x * 256 + threadIdx.x;
    int cnt = 0;
    if (idx < BB * (TT - 1)) {
        int b = idx / (TT - 1), t = idx % (TT - 1);
        int a = g_codes[(b*TT + t)*NQ + 0];
        int c = g_codes[(b*TT + t + 1)*NQ + 0];
        cnt = (a != c) ? 1 : 0;
    }
    __shared__ int red[256];
    red[threadIdx.x] = cnt;
    __syncthreads();
    for (int s = 128; s > 0; s >>= 1) {
        if (threadIdx.x < s) red[threadIdx.x] += red[threadIdx.x + s];
        __syncthreads();
    }
    if (threadIdx.x == 0 && red[0]) atomicAdd(&g_acc[4], (double)red[0]);
}

// ---------------- fused decoder (dec1 + relu + dec2 + recon loss), 8 chunks/block ----------------
__global__ __launch_bounds__(256) void k_dec(const float* __restrict__ w1,
                                             const float* __restrict__ b1,
                                             const float* __restrict__ w2,
                                             const float* __restrict__ b2) {
    extern __shared__ float sm[];
    float* insm = sm;                  // 8 * 660
    float* hsm  = sm + 8*660;          // 8 * 2560
    float* red  = hsm + 8*2560;        // 256
    int tid = threadIdx.x;
    int g0 = blockIdx.x * 8;

    for (int e = tid; e < 8*660; e += 256) {
        int ch = e / 660, rem = e % 660;
        int c = rem / 5, l = rem % 5;
        int g = g0 + ch;
        int b = g / COUNT_DEC, n = g % COUNT_DEC;
        int t = n*5 + l;
        float v;
        if (c < 128) v = g_qout[((size_t)b*TT + t)*LAT + c];
        else         v = (float)g_codes[(b*TT + t)*NQ + (c - 128)];
        insm[ch*660 + c*5 + l] = v;
    }
    __syncthreads();

    // phase 1: dec1 conv K=5 pad 2 over L=5, relu
    for (int op = 0; op < 2; op++) {
        int o = tid + op*256;
        float acc[8][5];
        float bbv = b1[o];
        #pragma unroll
        for (int ch = 0; ch < 8; ch++)
            #pragma unroll
            for (int l = 0; l < 5; l++) acc[ch][l] = bbv;
        for (int c = 0; c < 132; c++) {
            float inr[8][5];
            #pragma unroll
            for (int ch = 0; ch < 8; ch++)
                #pragma unroll
                for (int l = 0; l < 5; l++) inr[ch][l] = insm[ch*660 + c*5 + l];
            #pragma unroll
            for (int j = 0; j < 5; j++) {
                float wv = w1[((size_t)o*132 + c)*5 + j];
                #pragma unroll
                for (int l = 0; l < 5; l++) {
                    int p = l + j - 2;
                    if (p >= 0 && p < 5) {
                        #pragma unroll
                        for (int ch = 0; ch < 8; ch++) acc[ch][l] += wv * inr[ch][p];
                    }
                }
            }
        }
        #pragma unroll
        for (int ch = 0; ch < 8; ch++)
            #pragma unroll
            for (int l = 0; l < 5; l++)
                hsm[ch*2560 + o*5 + l] = fmaxf(acc[ch][l], 0.f);
    }
    __syncthreads();

    // phase 2: dec2 conv K=3 pad 1, subtract true chunk, square
    int o2 = tid & 127, gp = tid >> 7;
    float acc2[4][5];
    float bb2 = b2[o2];
    #pragma unroll
    for (int cc = 0; cc < 4; cc++)
        #pragma unroll
        for (int l = 0; l < 5; l++) acc2[cc][l] = bb2;
    for (int c = 0; c < 512; c++) {
        float hr[4][5];
        #pragma unroll
        for (int cc = 0; cc < 4; cc++)
            #pragma unroll
            for (int l = 0; l < 5; l++) hr[cc][l] = hsm[(gp*4 + cc)*2560 + c*5 + l];
        #pragma unroll
        for (int j = 0; j < 3; j++) {
            float wv = w2[((size_t)o2*512 + c)*3 + j];
            #pragma unroll
            for (int l = 0; l < 5; l++) {
                int p = l + j - 1;
                if (p >= 0 && p < 5) {
                    #pragma unroll
                    for (int cc = 0; cc < 4; cc++) acc2[cc][l] += wv * hr[cc][p];
                }
            }
        }
    }
    float lsum = 0.f;
    #pragma unroll
    for (int cc = 0; cc < 4; cc++) {
        int g = g0 + gp*4 + cc;
        int b = g / COUNT_DEC, n = g % COUNT_DEC;
        #pragma unroll
        for (int l = 0; l < 5; l++) {
            int t = (n + 1)*5 + l;
            float d = acc2[cc][l] - g_qout[((size_t)b*TT + t)*LAT + o2];
            lsum += d*d;
        }
    }
    red[tid] = lsum;
    __syncthreads();
    for (int s = 128; s > 0; s >>= 1) {
        if (tid < s) red[tid] += red[tid + s];
        __syncthreads();
    }
    if (tid == 0) atomicAdd(&g_acc[5], (double)red[0]);
}

// ---------------- outputs ----------------
__global__ void k_codes_out(float* __restrict__ out, int out_size) {
    int i = blockIdx.x * 256 + threadIdx.x;
    if (i < BB*TT*NQ && i < out_size) out[i] = (float)g_codes[i];
}

__global__ void k_final(float* __restrict__ out, int out_size) {
    if (threadIdx.x != 0 || blockIdx.x != 0) return;
    double nv = (double)BB * TT * LAT;                  // 16,384,000
    double vq = (g_acc[0]/nv + g_acc[1]/nv + g_acc[2]/nv + g_acc[3]/nv) / 4.0;
    double recon = g_acc[5] / ((double)NCHUNKS * LAT * 5);
    double smooth = g_acc[4] / ((double)BB * (TT - 1));
    double loss = recon * 1.0 + vq * 1.0 + smooth * 0.1;
    int base = BB*TT*NQ;
    if (base + 0 < out_size) out[base + 0] = (float)loss;
    if (base + 1 < out_size) out[base + 1] = (float)recon;
    if (base + 2 < out_size) out[base + 2] = (float)vq;
    if (base + 3 < out_size) out[base + 3] = (float)smooth;
}

// ---------------- launch ----------------
extern "C" void kernel_launch(void* const* d_in, const int* in_sizes, int n_in,
                              void* d_out, int out_size) {
    const float* traj = (const float*)d_in[0];
    // d_in[1] = masks (unused by reference forward)
    const float* e1w  = (const float*)d_in[2];
    const float* e1b  = (const float*)d_in[3];
    const float* e2aw = (const float*)d_in[4];
    const float* e2ab = (const float*)d_in[5];
    const float* e2bw = (const float*)d_in[6];
    const float* e2bb = (const float*)d_in[7];
    const float* d1w  = (const float*)d_in[8];
    const float* d1b  = (const float*)d_in[9];
    const float* d2w  = (const float*)d_in[10];
    const float* d2b  = (const float*)d_in[11];
    const float* cb   = (const float*)d_in[12];
    float* out = (float*)d_out;

    const int VQ_SMEM  = (64*132 + 128*132 + 128) * 4;      // 101,888 B
    const int DEC_SMEM = (8*660 + 8*2560 + 256) * 4;        // 104,064 B
    cudaFuncSetAttribute(k_vq,  cudaFuncAttributeMaxDynamicSharedMemorySize, VQ_SMEM);
    cudaFuncSetAttribute(k_dec, cudaFuncAttributeMaxDynamicSharedMemorySize, DEC_SMEM);

    void *p_z2 = nullptr, *p_z3 = nullptr, *p_ze = nullptr;
    cudaGetSymbolAddress(&p_z2, g_z2);
    cudaGetSymbolAddress(&p_z3, g_z3);
    cudaGetSymbolAddress(&p_ze, g_ze);

    k_zero_acc<<<1, 32>>>();
    k_enc1<<<dim3(TN/16, BB), 256>>>(traj, e1w, e1b);
    {
        size_t total = (size_t)BB*HID*TT;
        k_z2<<<(unsigned)(total / 256), 256>>>();
    }
    // enc2a: 512->512, K=5, relu
    k_conv<5, true, false><<<dim3(TT/64, HID/64, BB), 256>>>((const float*)p_z2, e2aw, e2ab, (float*)p_z3);
    // enc2b: 512->128, K=7, transposed out (B,T,128)
    k_conv<7, false, true><<<dim3(TT/64, LAT/64, BB), 256>>>((const float*)p_z3, e2bw, e2bb, (float*)p_ze);
    k_cbnorm<<<(NQ*KCB)/256, 256>>>(cb);
    for (int qi = 0; qi < NQ; qi++) {
        k_vq<<<(BB*TT)/64, 256, VQ_SMEM>>>(cb, qi);
    }
    k_smooth<<<(BB*(TT-1) + 255)/256, 256>>>();
    k_dec<<<NCHUNKS/8, 256, DEC_SMEM>>>(d1w, d1b, d2w, d2b);
    k_codes_out<<<(BB*TT*NQ)/256, 256>>>(out, out_size);
    k_final<<<1, 32>>>(out, out_size);
}

// round 5
// speedup vs baseline: 1.2955x; 1.2955x over previous
#include <cuda_runtime.h>
#include <math.h>

#define BB   16
#define TT   8000
#define TN   800
#define HID  512
#define LAT  128
#define KCB  1024
#define NQ   4
#define COUNT_DEC 1599
#define NCHUNKS   25584   // BB * COUNT_DEC
#define RESCORE_TAU 4e-3f

// ---------------- scratch (device globals; no allocation allowed) ----------------
__device__ float g_z1[BB*HID*TN];        // enc1 out (B,512,800)
__device__ float g_z3[(size_t)BB*HID*TT];// enc2a out (B,512,8000)
__device__ float g_ze[(size_t)BB*TT*LAT];// enc2b out, transposed (B,T,128)
__device__ float g_res[(size_t)BB*TT*LAT];
__device__ float g_qout[(size_t)BB*TT*LAT];
__device__ int   g_codes[BB*TT*NQ];
__device__ float g_cbn[NQ*KCB];
__device__ float g_w1t[132*5*512];       // dec1 weights transposed: [(c*5+j)*512 + o]
__device__ float g_w2t[512*3*128];       // dec2 weights transposed: [(c*3+j)*128 + o]
__device__ double g_acc[8];  // [0..3] vq sums, [4] smooth count, [5] recon sum

// ---------------- tiny utility kernels ----------------
__global__ void k_zero_acc() {
    if (threadIdx.x < 8) g_acc[threadIdx.x] = 0.0;
}

__global__ void k_tw1(const float* __restrict__ w1) {
    int idx = blockIdx.x * 256 + threadIdx.x;
    if (idx >= 512*660) return;
    int o = idx / 660, r = idx % 660;
    g_w1t[r*512 + o] = w1[idx];     // r = c*5 + j already
}
__global__ void k_tw2(const float* __restrict__ w2) {
    int idx = blockIdx.x * 256 + threadIdx.x;
    if (idx >= 128*1536) return;
    int o = idx / 1536, r = idx % 1536;
    g_w2t[r*128 + o] = w2[idx];     // r = c*3 + j already
}

// ---------------- enc1: (B,20,800) -> relu conv K=3 -> (B,512,800) ----------------
__global__ __launch_bounds__(256) void k_enc1(const float* __restrict__ traj,
                                              const float* __restrict__ w,
                                              const float* __restrict__ bias) {
    __shared__ float xs[20][18];
    int b = blockIdx.y, t0 = blockIdx.x * 16;
    int tid = threadIdx.x;
    for (int e = tid; e < 20*18; e += 256) {
        int i = e / 18, u = e % 18;
        int tg = t0 + u - 1;
        float v = 0.f;
        if (tg >= 0 && tg < TN) v = traj[((size_t)b*2 + (i/10))*TT + tg*10 + (i%10)];
        xs[i][u] = v;
    }
    __syncthreads();
    int o0 = tid, o1 = tid + 256;
    float acc0[16], acc1[16];
    float b0 = bias[o0], b1v = bias[o1];
    #pragma unroll
    for (int t = 0; t < 16; t++) { acc0[t] = 0.f; acc1[t] = 0.f; }
    for (int i = 0; i < 20; i++) {
        #pragma unroll
        for (int j = 0; j < 3; j++) {
            float w0 = w[(o0*20 + i)*3 + j];
            float w1 = w[(o1*20 + i)*3 + j];
            #pragma unroll
            for (int t = 0; t < 16; t++) {
                float x = xs[i][t + j];
                acc0[t] += w0 * x;
                acc1[t] += w1 * x;
            }
        }
    }
    #pragma unroll
    for (int t = 0; t < 16; t++) {
        g_z1[((size_t)b*HID + o0)*TN + t0 + t] = fmaxf(acc0[t] + b0, 0.f);
        g_z1[((size_t)b*HID + o1)*TN + t0 + t] = fmaxf(acc1[t] + b1v, 0.f);
    }
}

// ---------------- conv v2: 64T x 128OC tile, thread = 4T x 8OC ----------------
// INTERP: compute pooled+interp value from g_z1 on the fly (enc2a input).
template<int K, bool RELU, bool TROUT, bool INTERP>
__global__ __launch_bounds__(256) void k_conv2(const float* __restrict__ in,
                                               const float* __restrict__ wt,
                                               const float* __restrict__ bias,
                                               float* __restrict__ out) {
    constexpr int P   = (K - 1) / 2;
    constexpr int ZW  = 64 + K - 1;                    // 68 (K=5) / 70 (K=7)
    constexpr int ZWP = (ZW % 4 == 0) ? ZW : ZW + (4 - ZW % 4);  // 68 / 72
    constexpr int NZ4 = (K + 6) / 4;                   // 2 / 3
    constexpr int PW  = 132;                           // wsm pitch (4-way wr conflict, aligned reads)
    __shared__ float wsm[8 * K * PW];
    __shared__ float zsm[8 * ZWP];
    int tid = threadIdx.x;
    int tx = tid & 15, ty = tid >> 4;
    int t0 = blockIdx.x * 64, ob = blockIdx.y * 128, b = blockIdx.z;
    int OCt = gridDim.y * 128;
    int o = ob + ty * 8, tt = tx * 4;

    float acc[8][4], sum[8][4];
    #pragma unroll
    for (int c = 0; c < 8; c++)
        #pragma unroll
        for (int tl = 0; tl < 4; tl++) { acc[c][tl] = 0.f; sum[c][tl] = 0.f; }

    for (int chunk = 0; chunk < 64; chunk++) {
        int ic0 = chunk * 8;
        __syncthreads();
        // weights: contiguous global reads, strided smem writes (pitch 132)
        for (int e = tid; e < 8 * K * 128; e += 256) {
            int ol = e / (8 * K);
            int r  = e - ol * (8 * K);
            int i  = r / K, j = r - i * K;
            wsm[(i*K + j)*PW + ol] = wt[((size_t)(ob + ol)*512 + ic0 + i)*K + j];
        }
        // input tile
        for (int e = tid; e < 8 * ZW; e += 256) {
            int i = e / ZW, u = e - i * ZW;
            int tg = t0 + u - P;
            float v = 0.f;
            if (tg >= 0 && tg < TT) {
                if (INTERP) {
                    const float* row = g_z1 + ((size_t)b*HID + ic0 + i)*TN;
                    float src = fmaxf(((float)tg + 0.5f)*0.5f - 0.5f, 0.0f);
                    int i0 = (int)src;
                    int i1 = min(i0 + 1, 3999);
                    float frac = src - (float)i0;
                    float v0 = row[i0 / 5];
                    float v1 = row[i1 / 5];
                    v = v0 * (1.0f - frac) + v1 * frac;
                } else {
                    v = in[((size_t)b*HID + ic0 + i)*TT + tg];
                }
            }
            zsm[i*ZWP + u] = v;
        }
        __syncthreads();
        #pragma unroll
        for (int i = 0; i < 8; i++) {
            float zr[NZ4 * 4];
            #pragma unroll
            for (int q = 0; q < NZ4; q++)
                *(float4*)&zr[q*4] = *(const float4*)&zsm[i*ZWP + tt + q*4];
            #pragma unroll
            for (int j = 0; j < K; j++) {
                float4 wa = *(const float4*)&wsm[(i*K + j)*PW + ty*8];
                float4 wb = *(const float4*)&wsm[(i*K + j)*PW + ty*8 + 4];
                #pragma unroll
                for (int tl = 0; tl < 4; tl++) {
                    float z = zr[tl + j];
                    acc[0][tl] += wa.x * z;
                    acc[1][tl] += wa.y * z;
                    acc[2][tl] += wa.z * z;
                    acc[3][tl] += wa.w * z;
                    acc[4][tl] += wb.x * z;
                    acc[5][tl] += wb.y * z;
                    acc[6][tl] += wb.z * z;
                    acc[7][tl] += wb.w * z;
                }
            }
        }
        if ((chunk & 3) == 3) {   // flush short fp32 chains
            #pragma unroll
            for (int c = 0; c < 8; c++)
                #pragma unroll
                for (int tl = 0; tl < 4; tl++) { sum[c][tl] += acc[c][tl]; acc[c][tl] = 0.f; }
        }
    }

    float resv[8][4];
    #pragma unroll
    for (int c = 0; c < 8; c++) {
        float bv = bias[o + c];
        #pragma unroll
        for (int tl = 0; tl < 4; tl++) {
            float v = sum[c][tl] + bv;
            if (RELU) v = fmaxf(v, 0.f);
            resv[c][tl] = v;
        }
    }
    if (!TROUT) {
        #pragma unroll
        for (int c = 0; c < 8; c++) {
            float4 v = make_float4(resv[c][0], resv[c][1], resv[c][2], resv[c][3]);
            *(float4*)&out[((size_t)b*OCt + o + c)*TT + t0 + tt] = v;
        }
    } else {
        #pragma unroll
        for (int tl = 0; tl < 4; tl++) {
            float4 va = make_float4(resv[0][tl], resv[1][tl], resv[2][tl], resv[3][tl]);
            float4 vb = make_float4(resv[4][tl], resv[5][tl], resv[6][tl], resv[7][tl]);
            *(float4*)&out[((size_t)b*TT + t0 + tt + tl)*OCt + o]     = va;
            *(float4*)&out[((size_t)b*TT + t0 + tt + tl)*OCt + o + 4] = vb;
        }
    }
}

// ---------------- codebook squared norms (double, stored fp32) ----------------
__global__ void k_cbnorm(const float* __restrict__ cb) {
    int id = blockIdx.x * 256 + threadIdx.x;
    if (id >= NQ * KCB) return;
    const float* r = cb + (size_t)id * LAT;
    double s = 0.0;
    for (int d = 0; d < LAT; d++) {
        double v = (double)r[d];
        s += v * v;
    }
    g_cbn[id] = (float)s;
}

// ---------------- residual VQ, one codebook per launch ----------------
__global__ __launch_bounds__(256) void k_vq(const float* __restrict__ cb_all, int qi) {
    extern __shared__ float sm[];
    float* rsm = sm;                      // 64 x 132
    float* csm = sm + 64*132;             // 128 x 132
    float* nsm = csm + 128*132;           // 128
    int tid = threadIdx.x, lane = tid & 31, w = tid >> 5;
    int row0 = blockIdx.x * 64;
    const float* src = (qi == 0) ? g_ze : g_res;
    for (int e = tid; e < 64*32; e += 256) {
        int lr = e >> 5, d4 = (e & 31) * 4;
        float4 v = *(const float4*)&src[(size_t)(row0 + lr)*LAT + d4];
        *(float4*)&rsm[lr*132 + d4] = v;
    }
    const float* cbq = cb_all + (size_t)qi * KCB * LAT;
    float bestv[8], secv[8]; int besti[8];
    #pragma unroll
    for (int rr = 0; rr < 8; rr++) { bestv[rr] = 3.4e38f; secv[rr] = 3.4e38f; besti[rr] = 0; }

    for (int cc = 0; cc < 8; cc++) {
        __syncthreads();
        for (int e = tid; e < 128*32; e += 256) {
            int k = e >> 5, d4 = (e & 31) * 4;
            float4 v = *(const float4*)&cbq[(size_t)(cc*128 + k)*LAT + d4];
            *(float4*)&csm[k*132 + d4] = v;
        }
        if (tid < 128) nsm[tid] = g_cbn[qi*KCB + cc*128 + tid];
        __syncthreads();
        float acc[8][4];
        #pragma unroll
        for (int rr = 0; rr < 8; rr++)
            #pragma unroll
            for (int c = 0; c < 4; c++) acc[rr][c] = 0.f;
        #pragma unroll 2
        for (int d = 0; d < 128; d += 4) {
            float4 cv[4];
            #pragma unroll
            for (int c = 0; c < 4; c++) cv[c] = *(const float4*)&csm[(lane*4 + c)*132 + d];
            #pragma unroll
            for (int rr = 0; rr < 8; rr++) {
                float4 rv = *(const float4*)&rsm[(w*8 + rr)*132 + d];
                #pragma unroll
                for (int c = 0; c < 4; c++) {
                    acc[rr][c] += rv.x*cv[c].x + rv.y*cv[c].y + rv.z*cv[c].z + rv.w*cv[c].w;
                }
            }
        }
        #pragma unroll
        for (int rr = 0; rr < 8; rr++) {
            #pragma unroll
            for (int c = 0; c < 4; c++) {
                float dist = nsm[lane*4 + c] - 2.0f * acc[rr][c];
                int idx = cc*128 + lane*4 + c;
                if (dist < bestv[rr]) { secv[rr] = bestv[rr]; bestv[rr] = dist; besti[rr] = idx; }
                else if (dist < secv[rr]) { secv[rr] = dist; }
            }
        }
    }

    double dq_local = 0.0;
    for (int rr = 0; rr < 8; rr++) {
        float v1 = bestv[rr]; int i1 = besti[rr]; float v2 = secv[rr];
        #pragma unroll
        for (int off = 16; off > 0; off >>= 1) {
            float ov1 = __shfl_xor_sync(0xffffffffu, v1, off);
            int   oi1 = __shfl_xor_sync(0xffffffffu, i1, off);
            float ov2 = __shfl_xor_sync(0xffffffffu, v2, off);
            if (ov1 < v1 || (ov1 == v1 && oi1 < i1)) {
                v2 = fminf(v1, ov2);
                v1 = ov1; i1 = oi1;
            } else {
                v2 = fminf(v2, ov1);
            }
        }
        int ix = i1;
        int rloc = w*8 + rr;
        // ---- exact fp64 rescore when the fp32 margin is too small ----
        if (v2 - v1 < RESCORE_TAU) {
            double bd = 1e300; int bi = 0x7fffffff;
            for (int kk = 0; kk < 32; kk++) {
                int k = kk*32 + lane;
                const float* cr = cbq + (size_t)k * LAT;
                double s = 0.0;
                for (int d = 0; d < 128; d++) {
                    double cd = (double)cr[d];
                    double rd = (double)rsm[rloc*132 + d];
                    s += cd*cd - 2.0*rd*cd;
                }
                if (s < bd || (s == bd && k < bi)) { bd = s; bi = k; }
            }
            #pragma unroll
            for (int off = 16; off > 0; off >>= 1) {
                double ob = __shfl_xor_sync(0xffffffffu, bd, off);
                int    oi = __shfl_xor_sync(0xffffffffu, bi, off);
                if (ob < bd || (ob == bd && oi < bi)) { bd = ob; bi = oi; }
            }
            ix = bi;
        }

        int r = row0 + rloc;
        const float* q = cbq + (size_t)ix * LAT;
        float4 qv = *(const float4*)&q[lane*4];
        float4 rv = *(const float4*)&rsm[rloc*132 + lane*4];
        double r2 = (double)rv.x*rv.x + (double)rv.y*rv.y + (double)rv.z*rv.z + (double)rv.w*rv.w;
        double q2 = (double)qv.x*qv.x + (double)qv.y*qv.y + (double)qv.z*qv.z + (double)qv.w*qv.w;
        double rq = (double)rv.x*qv.x + (double)rv.y*qv.y + (double)rv.z*qv.z + (double)rv.w*qv.w;
        double dxd = (double)qv.x - rv.x, dyd = (double)qv.y - rv.y;
        double dzd = (double)qv.z - rv.z, dwd = (double)qv.w - rv.w;
        double dq = dxd*dxd + dyd*dyd + dzd*dzd + dwd*dwd;
        #pragma unroll
        for (int off = 16; off > 0; off >>= 1) {
            r2 += __shfl_xor_sync(0xffffffffu, r2, off);
            q2 += __shfl_xor_sync(0xffffffffu, q2, off);
            rq += __shfl_xor_sync(0xffffffffu, rq, off);
            dq += __shfl_xor_sync(0xffffffffu, dq, off);
        }
        double ns = sqrt(r2), nt = sqrt(q2);
        double ins = 1.0 / (ns + 1e-12), intq = 1.0 / (nt + 1e-12);
        double ru = r2 * ins;                                        // r . u
        double ss2 = r2*ins*ins + 2.0*rq*ins*intq + q2*intq*intq;    // ||u+qh||^2
        double wn = sqrt(ss2);
        double iw = 1.0 / (wn + 1e-12);
        double rs = ru + rq * intq;                                  // r . (u+qh)
        double rw = rs * iw;                                         // r . w
        double scale = nt * ins;
        float4 qrf;
        {
            double sx = (double)rv.x*ins + (double)qv.x*intq;
            double sy = (double)rv.y*ins + (double)qv.y*intq;
            double sz = (double)rv.z*ins + (double)qv.z*intq;
            double sw = (double)rv.w*ins + (double)qv.w*intq;
            qrf.x = (float)(((double)rv.x - 2.0*rw*(sx*iw) + 2.0*ru*((double)qv.x*intq)) * scale);
            qrf.y = (float)(((double)rv.y - 2.0*rw*(sy*iw) + 2.0*ru*((double)qv.y*intq)) * scale);
            qrf.z = (float)(((double)rv.z - 2.0*rw*(sz*iw) + 2.0*ru*((double)qv.z*intq)) * scale);
            qrf.w = (float)(((double)rv.w - 2.0*rw*(sw*iw) + 2.0*ru*((double)qv.w*intq)) * scale);
        }
        size_t base = (size_t)r * LAT + lane*4;
        if (qi == 0) {
            *(float4*)&g_qout[base] = qrf;
        } else {
            float4 old = *(const float4*)&g_qout[base];
            old.x += qrf.x; old.y += qrf.y; old.z += qrf.z; old.w += qrf.w;
            *(float4*)&g_qout[base] = old;
        }
        if (qi < 3) {
            float4 nr = make_float4(rv.x - qrf.x, rv.y - qrf.y, rv.z - qrf.z, rv.w - qrf.w);
            *(float4*)&g_res[base] = nr;
        }
        if (lane == 0) {
            g_codes[r*NQ + qi] = ix;
            dq_local += dq;
        }
    }
    if (lane == 0) atomicAdd(&g_acc[qi], dq_local);
}

// ---------------- smooth loss ----------------
__global__ void k_smooth() {
    int idx = blockIdx.x * 256 + threadIdx.x;
    int cnt = 0;
    if (idx < BB * (TT - 1)) {
        int b = idx / (TT - 1), t = idx % (TT - 1);
        int a = g_codes[(b*TT + t)*NQ + 0];
        int c = g_codes[(b*TT + t + 1)*NQ + 0];
        cnt = (a != c) ? 1 : 0;
    }
    __shared__ int red[256];
    red[threadIdx.x] = cnt;
    __syncthreads();
    for (int s = 128; s > 0; s >>= 1) {
        if (threadIdx.x < s) red[threadIdx.x] += red[threadIdx.x + s];
        __syncthreads();
    }
    if (threadIdx.x == 0 && red[0]) atomicAdd(&g_acc[4], (double)red[0]);
}

// ---------------- fused decoder (dec1 + relu + dec2 + recon loss), 8 chunks/block ----------------
__global__ __launch_bounds__(256) void k_dec(const float* __restrict__ b1,
                                             const float* __restrict__ b2) {
    extern __shared__ float sm[];
    float* insm = sm;                  // 8 * 660
    float* hsm  = sm + 8*660;          // 8 * 2560
    float* red  = hsm + 8*2560;        // 256
    int tid = threadIdx.x;
    int g0 = blockIdx.x * 8;

    for (int e = tid; e < 8*660; e += 256) {
        int ch = e / 660, rem = e % 660;
        int c = rem / 5, l = rem % 5;
        int g = g0 + ch;
        int b = g / COUNT_DEC, n = g % COUNT_DEC;
        int t = n*5 + l;
        float v;
        if (c < 128) v = g_qout[((size_t)b*TT + t)*LAT + c];
        else         v = (float)g_codes[(b*TT + t)*NQ + (c - 128)];
        insm[ch*660 + c*5 + l] = v;
    }
    __syncthreads();

    // phase 1: dec1 conv K=5 pad 2 over L=5, relu
    for (int op = 0; op < 2; op++) {
        int o = tid + op*256;
        float acc[8][5];
        float bbv = b1[o];
        #pragma unroll
        for (int ch = 0; ch < 8; ch++)
            #pragma unroll
            for (int l = 0; l < 5; l++) acc[ch][l] = bbv;
        for (int c = 0; c < 132; c++) {
            float inr[8][5];
            #pragma unroll
            for (int ch = 0; ch < 8; ch++)
                #pragma unroll
                for (int l = 0; l < 5; l++) inr[ch][l] = insm[ch*660 + c*5 + l];
            #pragma unroll
            for (int j = 0; j < 5; j++) {
                float wv = g_w1t[(c*5 + j)*512 + o];
                #pragma unroll
                for (int l = 0; l < 5; l++) {
                    int p = l + j - 2;
                    if (p >= 0 && p < 5) {
                        #pragma unroll
                        for (int ch = 0; ch < 8; ch++) acc[ch][l] += wv * inr[ch][p];
                    }
                }
            }
        }
        #pragma unroll
        for (int ch = 0; ch < 8; ch++)
            #pragma unroll
            for (int l = 0; l < 5; l++)
                hsm[ch*2560 + o*5 + l] = fmaxf(acc[ch][l], 0.f);
    }
    __syncthreads();

    // phase 2: dec2 conv K=3 pad 1, subtract true chunk, square
    int o2 = tid & 127, gp = tid >> 7;
    float acc2[4][5];
    float bb2 = b2[o2];
    #pragma unroll
    for (int cc = 0; cc < 4; cc++)
        #pragma unroll
        for (int l = 0; l < 5; l++) acc2[cc][l] = bb2;
    for (int c = 0; c < 512; c++) {
        float hr[4][5];
        #pragma unroll
        for (int cc = 0; cc < 4; cc++)
            #pragma unroll
            for (int l = 0; l < 5; l++) hr[cc][l] = hsm[(gp*4 + cc)*2560 + c*5 + l];
        #pragma unroll
        for (int j = 0; j < 3; j++) {
            float wv = g_w2t[(c*3 + j)*128 + o2];
            #pragma unroll
            for (int l = 0; l < 5; l++) {
                int p = l + j - 1;
                if (p >= 0 && p < 5) {
                    #pragma unroll
                    for (int cc = 0; cc < 4; cc++) acc2[cc][l] += wv * hr[cc][p];
                }
            }
        }
    }
    float lsum = 0.f;
    #pragma unroll
    for (int cc = 0; cc < 4; cc++) {
        int g = g0 + gp*4 + cc;
        int b = g / COUNT_DEC, n = g % COUNT_DEC;
        #pragma unroll
        for (int l = 0; l < 5; l++) {
            int t = (n + 1)*5 + l;
            float d = acc2[cc][l] - g_qout[((size_t)b*TT + t)*LAT + o2];
            lsum += d*d;
        }
    }
    red[tid] = lsum;
    __syncthreads();
    for (int s = 128; s > 0; s >>= 1) {
        if (tid < s) red[tid] += red[tid + s];
        __syncthreads();
    }
    if (tid == 0) atomicAdd(&g_acc[5], (double)red[0]);
}

// ---------------- outputs ----------------
__global__ void k_codes_out(float* __restrict__ out, int out_size) {
    int i = blockIdx.x * 256 + threadIdx.x;
    if (i < BB*TT*NQ && i < out_size) out[i] = (float)g_codes[i];
}

__global__ void k_final(float* __restrict__ out, int out_size) {
    if (threadIdx.x != 0 || blockIdx.x != 0) return;
    double nv = (double)BB * TT * LAT;                  // 16,384,000
    double vq = (g_acc[0]/nv + g_acc[1]/nv + g_acc[2]/nv + g_acc[3]/nv) / 4.0;
    double recon = g_acc[5] / ((double)NCHUNKS * LAT * 5);
    double smooth = g_acc[4] / ((double)BB * (TT - 1));
    double loss = recon * 1.0 + vq * 1.0 + smooth * 0.1;
    int base = BB*TT*NQ;
    if (base + 0 < out_size) out[base + 0] = (float)loss;
    if (base + 1 < out_size) out[base + 1] = (float)recon;
    if (base + 2 < out_size) out[base + 2] = (float)vq;
    if (base + 3 < out_size) out[base + 3] = (float)smooth;
}

// ---------------- launch ----------------
extern "C" void kernel_launch(void* const* d_in, const int* in_sizes, int n_in,
                              void* d_out, int out_size) {
    const float* traj = (const float*)d_in[0];
    // d_in[1] = masks (unused by reference forward)
    const float* e1w  = (const float*)d_in[2];
    const float* e1b  = (const float*)d_in[3];
    const float* e2aw = (const float*)d_in[4];
    const float* e2ab = (const float*)d_in[5];
    const float* e2bw = (const float*)d_in[6];
    const float* e2bb = (const float*)d_in[7];
    const float* d1w  = (const float*)d_in[8];
    const float* d1b  = (const float*)d_in[9];
    const float* d2w  = (const float*)d_in[10];
    const float* d2b  = (const float*)d_in[11];
    const float* cb   = (const float*)d_in[12];
    float* out = (float*)d_out;

    const int VQ_SMEM  = (64*132 + 128*132 + 128) * 4;      // 101,888 B
    const int DEC_SMEM = (8*660 + 8*2560 + 256) * 4;        // 104,064 B
    cudaFuncSetAttribute(k_vq,  cudaFuncAttributeMaxDynamicSharedMemorySize, VQ_SMEM);
    cudaFuncSetAttribute(k_dec, cudaFuncAttributeMaxDynamicSharedMemorySize, DEC_SMEM);

    void *p_z3 = nullptr, *p_ze = nullptr;
    cudaGetSymbolAddress(&p_z3, g_z3);
    cudaGetSymbolAddress(&p_ze, g_ze);

    k_zero_acc<<<1, 32>>>();
    k_tw1<<<(512*660 + 255)/256, 256>>>(d1w);
    k_tw2<<<(128*1536 + 255)/256, 256>>>(d2w);
    k_cbnorm<<<(NQ*KCB)/256, 256>>>(cb);
    k_enc1<<<dim3(TN/16, BB), 256>>>(traj, e1w, e1b);
    // enc2a: 512->512, K=5, relu, interp-fused input
    k_conv2<5, true, false, true><<<dim3(TT/64, HID/128, BB), 256>>>(nullptr, e2aw, e2ab, (float*)p_z3);
    // enc2b: 512->128, K=7, transposed out (B,T,128)
    k_conv2<7, false, true, false><<<dim3(TT/64, LAT/128, BB), 256>>>((const float*)p_z3, e2bw, e2bb, (float*)p_ze);
    for (int qi = 0; qi < NQ; qi++) {
        k_vq<<<(BB*TT)/64, 256, VQ_SMEM>>>(cb, qi);
    }
    k_smooth<<<(BB*(TT-1) + 255)/256, 256>>>();
    k_dec<<<NCHUNKS/8, 256, DEC_SMEM>>>(d1b, d2b);
    k_codes_out<<<(BB*TT*NQ)/256, 256>>>(out, out_size);
    k_final<<<1, 32>>>(out, out_size);
}